// round 2
// baseline (speedup 1.0000x reference)
#include <cuda_runtime.h>
#include <cuda_bf16.h>

// Problem constants (fixed shapes from reference)
#define T_TOK 32768
#define H_DIM 2048
#define I_DIM 768

// Scratch for intermediate activation x = silu(gate)*up : [T, I] fp32 (96 MB)
__device__ float g_x[(size_t)T_TOK * I_DIM];

// ---------------------------------------------------------------------------
// Kernel 1: gate_up GEMM fused with SiLU*Mul.
//   A = hidden_states [T, H] row-major
//   W = w_gate_up     [H, 2I] row-major (cols [0:I]=gate, [I:2I]=up)
//   X = g_x           [T, I]
// Tiling: BM=128, BN=64, BK=16. 256 threads, per-thread microtile 8(M)x4(N),
// with BOTH gate and up accumulators (A tile shared between the two B tiles).
// ---------------------------------------------------------------------------
__global__ __launch_bounds__(256, 2)
void gateup_silu_kernel(const float* __restrict__ A,
                        const float* __restrict__ W,
                        float* __restrict__ X)
{
    constexpr int BM = 128, BN = 64, BK = 16;
    constexpr int AP = 130;  // pad to kill store bank conflicts ((k*130)%32 spreads)

    __shared__ float As[BK][AP];   // transposed A tile: As[k][m]
    __shared__ float Bg[BK][BN];   // gate weights tile
    __shared__ float Bu[BK][BN];   // up weights tile

    const int bm = blockIdx.y * BM;
    const int bn = blockIdx.x * BN;
    const int tid = threadIdx.x;
    const int tx = tid & 15;   // N dim: 16 threads
    const int ty = tid >> 4;   // M dim: 16 threads

    float accg[8][4];
    float accu[8][4];
#pragma unroll
    for (int i = 0; i < 8; i++)
#pragma unroll
        for (int j = 0; j < 4; j++) { accg[i][j] = 0.f; accu[i][j] = 0.f; }

    for (int k0 = 0; k0 < H_DIM; k0 += BK) {
        // --- load A tile [BM x BK] as float4, store transposed ---
#pragma unroll
        for (int l = 0; l < 2; l++) {
            int f   = tid + l * 256;      // 0..511
            int row = f >> 2;             // 0..127
            int c4  = f & 3;              // 0..3 (which float4 in the row)
            float4 v = *reinterpret_cast<const float4*>(
                &A[(size_t)(bm + row) * H_DIM + k0 + c4 * 4]);
            As[c4 * 4 + 0][row] = v.x;
            As[c4 * 4 + 1][row] = v.y;
            As[c4 * 4 + 2][row] = v.z;
            As[c4 * 4 + 3][row] = v.w;
        }
        // --- load B tiles [BK x BN] for gate and up ---
        {
            int row = tid >> 4;  // 0..15 (k)
            int c4  = tid & 15;  // 0..15 (float4 within 64-wide row)
            const float* wrow = &W[(size_t)(k0 + row) * (2 * I_DIM)];
            float4 vg = *reinterpret_cast<const float4*>(&wrow[bn + c4 * 4]);
            float4 vu = *reinterpret_cast<const float4*>(&wrow[I_DIM + bn + c4 * 4]);
            *reinterpret_cast<float4*>(&Bg[row][c4 * 4]) = vg;
            *reinterpret_cast<float4*>(&Bu[row][c4 * 4]) = vu;
        }
        __syncthreads();

#pragma unroll
        for (int k = 0; k < BK; k++) {
            float a[8];
#pragma unroll
            for (int i = 0; i < 8; i++) a[i] = As[k][ty * 8 + i];
            float4 bg4 = *reinterpret_cast<float4*>(&Bg[k][tx * 4]);
            float4 bu4 = *reinterpret_cast<float4*>(&Bu[k][tx * 4]);
            float bg[4] = {bg4.x, bg4.y, bg4.z, bg4.w};
            float bu[4] = {bu4.x, bu4.y, bu4.z, bu4.w};
#pragma unroll
            for (int i = 0; i < 8; i++) {
#pragma unroll
                for (int j = 0; j < 4; j++) {
                    accg[i][j] = fmaf(a[i], bg[j], accg[i][j]);
                    accu[i][j] = fmaf(a[i], bu[j], accu[i][j]);
                }
            }
        }
        __syncthreads();
    }

    // --- epilogue: silu(gate) * up ---
#pragma unroll
    for (int i = 0; i < 8; i++) {
        int trow = bm + ty * 8 + i;
        float* xrow = &X[(size_t)trow * I_DIM + bn + tx * 4];
#pragma unroll
        for (int j = 0; j < 4; j++) {
            float g = accg[i][j];
            float u = accu[i][j];
            float sig = 1.0f / (1.0f + __expf(-g));
            xrow[j] = g * sig * u;
        }
    }
}

// ---------------------------------------------------------------------------
// Kernel 2: down projection GEMM.
//   X  = g_x    [T, I] row-major
//   Wd = w_down [I, H] row-major
//   O  = out    [T, H]
// Tiling: BM=128, BN=128, BK=16. 256 threads, per-thread microtile 8x8.
// ---------------------------------------------------------------------------
__global__ __launch_bounds__(256, 2)
void down_kernel(const float* __restrict__ X,
                 const float* __restrict__ Wd,
                 float* __restrict__ O)
{
    constexpr int BM = 128, BN = 128, BK = 16;
    constexpr int AP = 130;

    __shared__ float As[BK][AP];   // transposed X tile: As[k][m]
    __shared__ float Bs[BK][BN];   // Wd tile

    const int bm = blockIdx.y * BM;
    const int bn = blockIdx.x * BN;
    const int tid = threadIdx.x;
    const int tx = tid & 15;   // N
    const int ty = tid >> 4;   // M

    float acc[8][8];
#pragma unroll
    for (int i = 0; i < 8; i++)
#pragma unroll
        for (int j = 0; j < 8; j++) acc[i][j] = 0.f;

    for (int k0 = 0; k0 < I_DIM; k0 += BK) {
        // A tile [BM x BK] -> transposed
#pragma unroll
        for (int l = 0; l < 2; l++) {
            int f   = tid + l * 256;
            int row = f >> 2;
            int c4  = f & 3;
            float4 v = *reinterpret_cast<const float4*>(
                &X[(size_t)(bm + row) * I_DIM + k0 + c4 * 4]);
            As[c4 * 4 + 0][row] = v.x;
            As[c4 * 4 + 1][row] = v.y;
            As[c4 * 4 + 2][row] = v.z;
            As[c4 * 4 + 3][row] = v.w;
        }
        // B tile [BK x BN]: 512 float4, 2 per thread
#pragma unroll
        for (int l = 0; l < 2; l++) {
            int f   = tid + l * 256;   // 0..511
            int row = f >> 5;          // 0..15
            int c4  = f & 31;          // 0..31
            float4 v = *reinterpret_cast<const float4*>(
                &Wd[(size_t)(k0 + row) * H_DIM + bn + c4 * 4]);
            *reinterpret_cast<float4*>(&Bs[row][c4 * 4]) = v;
        }
        __syncthreads();

#pragma unroll
        for (int k = 0; k < BK; k++) {
            float a[8];
#pragma unroll
            for (int i = 0; i < 8; i++) a[i] = As[k][ty * 8 + i];
            float4 b0 = *reinterpret_cast<float4*>(&Bs[k][tx * 8]);
            float4 b1 = *reinterpret_cast<float4*>(&Bs[k][tx * 8 + 4]);
            float b[8] = {b0.x, b0.y, b0.z, b0.w, b1.x, b1.y, b1.z, b1.w};
#pragma unroll
            for (int i = 0; i < 8; i++)
#pragma unroll
                for (int j = 0; j < 8; j++)
                    acc[i][j] = fmaf(a[i], b[j], acc[i][j]);
        }
        __syncthreads();
    }

#pragma unroll
    for (int i = 0; i < 8; i++) {
        int trow = bm + ty * 8 + i;
        float* orow = &O[(size_t)trow * H_DIM + bn + tx * 8];
#pragma unroll
        for (int j = 0; j < 8; j++) orow[j] = acc[i][j];
    }
}

extern "C" void kernel_launch(void* const* d_in, const int* in_sizes, int n_in,
                              void* d_out, int out_size)
{
    const float* hidden   = (const float*)d_in[0];  // [T, H]
    const float* w_gateup = (const float*)d_in[1];  // [H, 2I]
    const float* w_down   = (const float*)d_in[2];  // [I, H]
    float* out = (float*)d_out;                     // [T, H]

    float* x;
    cudaGetSymbolAddress((void**)&x, g_x);

    // Kernel 1: [T,H] @ [H,2I] fused SiLU*Mul -> x [T, I]
    {
        dim3 grid(I_DIM / 64, T_TOK / 128);
        gateup_silu_kernel<<<grid, 256>>>(hidden, w_gateup, x);
    }
    // Kernel 2: x [T,I] @ [I,H] -> out [T, H]
    {
        dim3 grid(H_DIM / 128, T_TOK / 128);
        down_kernel<<<grid, 256>>>(x, w_down, out);
    }
}

// round 4
// speedup vs baseline: 2.0537x; 2.0537x over previous
#include <cuda_runtime.h>
#include <cuda_bf16.h>
#include <cstdint>

#define T_TOK 32768
#define H_DIM 2048
#define I_DIM 768

using bf16 = __nv_bfloat16;

// ---------------- static device scratch ------------------------------------
__device__ bf16 g_Ahi[(size_t)T_TOK * H_DIM];
__device__ bf16 g_Alo[(size_t)T_TOK * H_DIM];
__device__ bf16 g_Wgu_hi[(size_t)2 * I_DIM * H_DIM];   // w_gate_up^T  [2I, H]
__device__ bf16 g_Wgu_lo[(size_t)2 * I_DIM * H_DIM];
__device__ bf16 g_Wd_hi[(size_t)H_DIM * I_DIM];        // w_down^T     [H, I]
__device__ bf16 g_Wd_lo[(size_t)H_DIM * I_DIM];
__device__ bf16 g_Xhi[(size_t)T_TOK * I_DIM];          // silu(g)*u    [T, I]
__device__ bf16 g_Xlo[(size_t)T_TOK * I_DIM];

// ---------------- helpers ----------------------------------------------------
__device__ __forceinline__ uint32_t smem_u32(const void* p) {
    return (uint32_t)__cvta_generic_to_shared(p);
}
__device__ __forceinline__ void cp16(uint32_t dst, const void* src) {
    asm volatile("cp.async.cg.shared.global [%0], [%1], 16;" :: "r"(dst), "l"(src));
}
__device__ __forceinline__ void cp_commit() {
    asm volatile("cp.async.commit_group;" ::: "memory");
}
template <int N>
__device__ __forceinline__ void cp_wait() {
    asm volatile("cp.async.wait_group %0;" :: "n"(N) : "memory");
}
__device__ __forceinline__ void ldsm_x4(uint32_t* r, uint32_t addr) {
    asm volatile("ldmatrix.sync.aligned.m8n8.x4.shared.b16 {%0,%1,%2,%3}, [%4];"
                 : "=r"(r[0]), "=r"(r[1]), "=r"(r[2]), "=r"(r[3]) : "r"(addr));
}
__device__ __forceinline__ void mma16816(float* d, const uint32_t* a,
                                         uint32_t b0, uint32_t b1) {
    asm volatile(
        "mma.sync.aligned.m16n8k16.row.col.f32.bf16.bf16.f32 "
        "{%0,%1,%2,%3}, {%4,%5,%6,%7}, {%8,%9}, {%0,%1,%2,%3};"
        : "+f"(d[0]), "+f"(d[1]), "+f"(d[2]), "+f"(d[3])
        : "r"(a[0]), "r"(a[1]), "r"(a[2]), "r"(a[3]), "r"(b0), "r"(b1));
}
__device__ __forceinline__ uint32_t pk2(bf16 a, bf16 b) {
    __nv_bfloat162 t; t.x = a; t.y = b;
    return *reinterpret_cast<uint32_t*>(&t);
}
__device__ __forceinline__ void split1(float a, bf16& h, bf16& l) {
    h = __float2bfloat16_rn(a);
    l = __float2bfloat16_rn(a - __bfloat162float(h));
}

// SMEM stage layout (pad rows to 80B to kill ldmatrix bank conflicts):
//   Ahi @0 (128x80=10240), Alo @10240, Bhi @20480 (128x80), Blo @30720
#define ROWB        80
#define STAGE_BYTES 40960
#define NSTAGE      3
#define SMEM_BYTES  (NSTAGE * STAGE_BYTES)

// ============================================================================
// GEMM1: hidden[T,H] x Wgu^T[2I,H] -> silu(gate)*up -> Xhi/Xlo [T,I]
// CTA: 128 tokens x 64 I-cols (gate + up). 8 warps (2 m x 4 n), warp 64x16 x2.
// ============================================================================
__device__ __forceinline__ void g1_load_stage(
    uint32_t SB, int k0, int bm, int nt,
    const bf16* __restrict__ Ahi, const bf16* __restrict__ Alo,
    const bf16* __restrict__ Wh,  const bf16* __restrict__ Wl, int tid)
{
#pragma unroll
    for (int c = tid; c < 512; c += 256) {            // A: 128 rows x 4 chunks
        int row = c >> 2, kc = c & 3;
        uint32_t d = SB + row * ROWB + kc * 16;
        size_t gof = (size_t)(bm + row) * H_DIM + k0 + kc * 8;
        cp16(d,         Ahi + gof);
        cp16(d + 10240, Alo + gof);
    }
#pragma unroll
    for (int c = tid; c < 512; c += 256) {            // B: 64 gate + 64 up rows
        int row = c >> 2, kc = c & 3;
        int gr = (row < 64) ? (nt * 64 + row) : (I_DIM + nt * 64 + row - 64);
        uint32_t d = SB + 20480 + row * ROWB + kc * 16;
        size_t gof = (size_t)gr * H_DIM + k0 + kc * 8;
        cp16(d,         Wh + gof);
        cp16(d + 10240, Wl + gof);
    }
}

__global__ __launch_bounds__(256, 1)
void gemm1_k(const bf16* __restrict__ Ahi, const bf16* __restrict__ Alo,
             const bf16* __restrict__ Wh,  const bf16* __restrict__ Wl,
             bf16* __restrict__ Xhi, bf16* __restrict__ Xlo)
{
    extern __shared__ char smem[];
    const uint32_t sb = smem_u32(smem);
    const int tid = threadIdx.x, wid = tid >> 5, lane = tid & 31;
    const int warp_m = wid & 1, warp_n = wid >> 1;
    const int nt = blockIdx.x;                  // 0..11 (64 I-cols each)
    const int bm = blockIdx.y * 128;
    const int NITER = H_DIM / 32;               // 64

    float accg[4][2][4], accu[4][2][4];
#pragma unroll
    for (int mi = 0; mi < 4; mi++)
#pragma unroll
        for (int ni = 0; ni < 2; ni++)
#pragma unroll
            for (int v = 0; v < 4; v++) { accg[mi][ni][v] = 0.f; accu[mi][ni][v] = 0.f; }

    g1_load_stage(sb, 0, bm, nt, Ahi, Alo, Wh, Wl, tid); cp_commit();
    g1_load_stage(sb + STAGE_BYTES, 32, bm, nt, Ahi, Alo, Wh, Wl, tid); cp_commit();

    const int arow = lane & 15;
    const int acol = (lane >> 4) * 16;
    const int brow = (lane & 7) + ((lane >> 4) << 3);
    const int bcol = ((lane >> 3) & 1) * 16;

    for (int it = 0; it < NITER; ++it) {
        cp_wait<1>();
        __syncthreads();
        if (it + 2 < NITER) {
            g1_load_stage(sb + ((it + 2) % NSTAGE) * STAGE_BYTES, (it + 2) * 32,
                          bm, nt, Ahi, Alo, Wh, Wl, tid);
        }
        cp_commit();   // keep group count in lockstep even when empty

        uint32_t SB = sb + (it % NSTAGE) * STAGE_BYTES;
#pragma unroll
        for (int ks = 0; ks < 2; ks++) {
            uint32_t ah[4][4], al[4][4];
#pragma unroll
            for (int mi = 0; mi < 4; mi++) {
                uint32_t ra = SB + (warp_m * 64 + mi * 16 + arow) * ROWB + ks * 32 + acol;
                ldsm_x4(ah[mi], ra);
                ldsm_x4(al[mi], ra + 10240);
            }
            uint32_t rb = SB + 20480 + (warp_n * 16 + brow) * ROWB + ks * 32 + bcol;
            uint32_t bgh[4], bgl[4], buh[4], bul[4];
            ldsm_x4(bgh, rb);
            ldsm_x4(bgl, rb + 10240);
            ldsm_x4(buh, rb + 64 * ROWB);
            ldsm_x4(bul, rb + 64 * ROWB + 10240);
#pragma unroll
            for (int mi = 0; mi < 4; mi++)
#pragma unroll
                for (int ni = 0; ni < 2; ni++) {
                    mma16816(accg[mi][ni], ah[mi], bgh[ni*2], bgh[ni*2+1]);
                    mma16816(accg[mi][ni], ah[mi], bgl[ni*2], bgl[ni*2+1]);
                    mma16816(accg[mi][ni], al[mi], bgh[ni*2], bgh[ni*2+1]);
                    mma16816(accu[mi][ni], ah[mi], buh[ni*2], buh[ni*2+1]);
                    mma16816(accu[mi][ni], ah[mi], bul[ni*2], bul[ni*2+1]);
                    mma16816(accu[mi][ni], al[mi], buh[ni*2], buh[ni*2+1]);
                }
        }
        __syncthreads();
    }

    // epilogue: silu(gate)*up, split, store packed pairs
    const int g = lane >> 2, t = lane & 3;
#pragma unroll
    for (int mi = 0; mi < 4; mi++)
#pragma unroll
        for (int ni = 0; ni < 2; ni++) {
            int col = nt * 64 + warp_n * 16 + ni * 8 + t * 2;
            int row0 = bm + warp_m * 64 + mi * 16 + g;
#pragma unroll
            for (int h = 0; h < 2; h++) {           // h=0: c0,c1 ; h=1: c2,c3
                int row = row0 + h * 8;
                float g0 = accg[mi][ni][h*2],   g1 = accg[mi][ni][h*2+1];
                float u0 = accu[mi][ni][h*2],   u1 = accu[mi][ni][h*2+1];
                float x0 = u0 * g0 / (1.0f + __expf(-g0));
                float x1 = u1 * g1 / (1.0f + __expf(-g1));
                bf16 h0, l0, h1, l1;
                split1(x0, h0, l0); split1(x1, h1, l1);
                size_t o = (size_t)row * I_DIM + col;
                *reinterpret_cast<uint32_t*>(Xhi + o) = pk2(h0, h1);
                *reinterpret_cast<uint32_t*>(Xlo + o) = pk2(l0, l1);
            }
        }
}

// ============================================================================
// GEMM2: X[T,I] x Wd^T[H,I] -> out[T,H] fp32
// CTA: 128 tokens x 128 H-cols. 8 warps (2 m x 4 n), warp 64x32.
// ============================================================================
__device__ __forceinline__ void g2_load_stage(
    uint32_t SB, int k0, int bm, int bn,
    const bf16* __restrict__ Xh, const bf16* __restrict__ Xl,
    const bf16* __restrict__ Dh, const bf16* __restrict__ Dl, int tid)
{
#pragma unroll
    for (int c = tid; c < 512; c += 256) {
        int row = c >> 2, kc = c & 3;
        uint32_t d = SB + row * ROWB + kc * 16;
        size_t gof = (size_t)(bm + row) * I_DIM + k0 + kc * 8;
        cp16(d,         Xh + gof);
        cp16(d + 10240, Xl + gof);
    }
#pragma unroll
    for (int c = tid; c < 512; c += 256) {
        int row = c >> 2, kc = c & 3;
        uint32_t d = SB + 20480 + row * ROWB + kc * 16;
        size_t gof = (size_t)(bn + row) * I_DIM + k0 + kc * 8;
        cp16(d,         Dh + gof);
        cp16(d + 10240, Dl + gof);
    }
}

__global__ __launch_bounds__(256, 1)
void gemm2_k(const bf16* __restrict__ Xh, const bf16* __restrict__ Xl,
             const bf16* __restrict__ Dh, const bf16* __restrict__ Dl,
             float* __restrict__ out)
{
    extern __shared__ char smem[];
    const uint32_t sb = smem_u32(smem);
    const int tid = threadIdx.x, wid = tid >> 5, lane = tid & 31;
    const int warp_m = wid & 1, warp_n = wid >> 1;
    const int bn = blockIdx.x * 128;
    const int bm = blockIdx.y * 128;
    const int NITER = I_DIM / 32;               // 24

    float acc[4][4][4];
#pragma unroll
    for (int mi = 0; mi < 4; mi++)
#pragma unroll
        for (int ni = 0; ni < 4; ni++)
#pragma unroll
            for (int v = 0; v < 4; v++) acc[mi][ni][v] = 0.f;

    g2_load_stage(sb, 0, bm, bn, Xh, Xl, Dh, Dl, tid); cp_commit();
    g2_load_stage(sb + STAGE_BYTES, 32, bm, bn, Xh, Xl, Dh, Dl, tid); cp_commit();

    const int arow = lane & 15;
    const int acol = (lane >> 4) * 16;
    const int brow = (lane & 7) + ((lane >> 4) << 3);
    const int bcol = ((lane >> 3) & 1) * 16;

    for (int it = 0; it < NITER; ++it) {
        cp_wait<1>();
        __syncthreads();
        if (it + 2 < NITER) {
            g2_load_stage(sb + ((it + 2) % NSTAGE) * STAGE_BYTES, (it + 2) * 32,
                          bm, bn, Xh, Xl, Dh, Dl, tid);
        }
        cp_commit();

        uint32_t SB = sb + (it % NSTAGE) * STAGE_BYTES;
#pragma unroll
        for (int ks = 0; ks < 2; ks++) {
            uint32_t ah[4][4], al[4][4];
#pragma unroll
            for (int mi = 0; mi < 4; mi++) {
                uint32_t ra = SB + (warp_m * 64 + mi * 16 + arow) * ROWB + ks * 32 + acol;
                ldsm_x4(ah[mi], ra);
                ldsm_x4(al[mi], ra + 10240);
            }
            // B: 32 cols per warp = 4 n8 tiles = 2 ldmatrix.x4 (hi) + 2 (lo)
            uint32_t bh[8], bl[8];
#pragma unroll
            for (int bq = 0; bq < 2; bq++) {
                uint32_t rb = SB + 20480 + (warp_n * 32 + bq * 16 + brow) * ROWB + ks * 32 + bcol;
                ldsm_x4(&bh[bq*4], rb);
                ldsm_x4(&bl[bq*4], rb + 10240);
            }
#pragma unroll
            for (int mi = 0; mi < 4; mi++)
#pragma unroll
                for (int ni = 0; ni < 4; ni++) {
                    mma16816(acc[mi][ni], ah[mi], bh[ni*2], bh[ni*2+1]);
                    mma16816(acc[mi][ni], ah[mi], bl[ni*2], bl[ni*2+1]);
                    mma16816(acc[mi][ni], al[mi], bh[ni*2], bh[ni*2+1]);
                }
        }
        __syncthreads();
    }

    const int g = lane >> 2, t = lane & 3;
#pragma unroll
    for (int mi = 0; mi < 4; mi++)
#pragma unroll
        for (int ni = 0; ni < 4; ni++) {
            int col = bn + warp_n * 32 + ni * 8 + t * 2;
            int row0 = bm + warp_m * 64 + mi * 16 + g;
            float2 v0 = make_float2(acc[mi][ni][0], acc[mi][ni][1]);
            float2 v1 = make_float2(acc[mi][ni][2], acc[mi][ni][3]);
            *reinterpret_cast<float2*>(out + (size_t)row0 * H_DIM + col) = v0;
            *reinterpret_cast<float2*>(out + (size_t)(row0 + 8) * H_DIM + col) = v1;
        }
}

// ---------------- prep kernels ----------------------------------------------
__global__ void split_hidden_k(const float* __restrict__ in,
                               bf16* __restrict__ hi, bf16* __restrict__ lo)
{
    size_t i = (size_t)blockIdx.x * blockDim.x + threadIdx.x;
    float4 v = reinterpret_cast<const float4*>(in)[i];
    bf16 h0, l0, h1, l1, h2, l2, h3, l3;
    split1(v.x, h0, l0); split1(v.y, h1, l1);
    split1(v.z, h2, l2); split1(v.w, h3, l3);
    uint2 ph; ph.x = pk2(h0, h1); ph.y = pk2(h2, h3);
    uint2 pl; pl.x = pk2(l0, l1); pl.y = pk2(l2, l3);
    reinterpret_cast<uint2*>(hi)[i] = ph;
    reinterpret_cast<uint2*>(lo)[i] = pl;
}

__global__ void transpose_split_k(const float* __restrict__ in,
                                  bf16* __restrict__ ohi, bf16* __restrict__ olo,
                                  int R, int C)
{
    __shared__ float t[32][33];
    int bx = blockIdx.x * 32, by = blockIdx.y * 32;
    int tx = threadIdx.x, ty = threadIdx.y;
#pragma unroll
    for (int j = 0; j < 32; j += 8)
        t[ty + j][tx] = in[(size_t)(by + ty + j) * C + bx + tx];
    __syncthreads();
#pragma unroll
    for (int j = 0; j < 32; j += 8) {
        float a = t[tx][ty + j];
        bf16 h, l; split1(a, h, l);
        size_t o = (size_t)(bx + ty + j) * R + by + tx;
        ohi[o] = h; olo[o] = l;
    }
}

// ---------------- host ------------------------------------------------------
extern "C" void kernel_launch(void* const* d_in, const int* in_sizes, int n_in,
                              void* d_out, int out_size)
{
    const float* hidden = (const float*)d_in[0];   // [T, H]
    const float* wgu    = (const float*)d_in[1];   // [H, 2I]
    const float* wd     = (const float*)d_in[2];   // [I, H]
    float* out = (float*)d_out;                    // [T, H]

    bf16 *Ahi, *Alo, *Wh, *Wl, *Dh, *Dl, *Xh, *Xl;
    cudaGetSymbolAddress((void**)&Ahi, g_Ahi);
    cudaGetSymbolAddress((void**)&Alo, g_Alo);
    cudaGetSymbolAddress((void**)&Wh,  g_Wgu_hi);
    cudaGetSymbolAddress((void**)&Wl,  g_Wgu_lo);
    cudaGetSymbolAddress((void**)&Dh,  g_Wd_hi);
    cudaGetSymbolAddress((void**)&Dl,  g_Wd_lo);
    cudaGetSymbolAddress((void**)&Xh,  g_Xhi);
    cudaGetSymbolAddress((void**)&Xl,  g_Xlo);

    cudaFuncSetAttribute(gemm1_k, cudaFuncAttributeMaxDynamicSharedMemorySize, SMEM_BYTES);
    cudaFuncSetAttribute(gemm2_k, cudaFuncAttributeMaxDynamicSharedMemorySize, SMEM_BYTES);

    split_hidden_k<<<(int)(((size_t)T_TOK * H_DIM / 4) / 256), 256>>>(hidden, Ahi, Alo);
    transpose_split_k<<<dim3(2 * I_DIM / 32, H_DIM / 32), dim3(32, 8)>>>(wgu, Wh, Wl, H_DIM, 2 * I_DIM);
    transpose_split_k<<<dim3(H_DIM / 32, I_DIM / 32), dim3(32, 8)>>>(wd, Dh, Dl, I_DIM, H_DIM);

    gemm1_k<<<dim3(I_DIM / 64, T_TOK / 128), 256, SMEM_BYTES>>>(Ahi, Alo, Wh, Wl, Xh, Xl);
    gemm2_k<<<dim3(H_DIM / 128, T_TOK / 128), 256, SMEM_BYTES>>>(Xh, Xl, Dh, Dl, out);
}

// round 5
// speedup vs baseline: 2.1008x; 1.0230x over previous
#include <cuda_runtime.h>
#include <cuda_bf16.h>
#include <cstdint>

#define T_TOK 32768
#define H_DIM 2048
#define I_DIM 768

using bf16 = __nv_bfloat16;

// ---------------- static device scratch ------------------------------------
__device__ bf16 g_Ahi[(size_t)T_TOK * H_DIM];
__device__ bf16 g_Alo[(size_t)T_TOK * H_DIM];
__device__ bf16 g_Wgu_hi[(size_t)2 * I_DIM * H_DIM];   // w_gate_up^T  [2I, H]
__device__ bf16 g_Wgu_lo[(size_t)2 * I_DIM * H_DIM];
__device__ bf16 g_Wd_hi[(size_t)H_DIM * I_DIM];        // w_down^T     [H, I]
__device__ bf16 g_Wd_lo[(size_t)H_DIM * I_DIM];
__device__ bf16 g_Xhi[(size_t)T_TOK * I_DIM];          // silu(g)*u    [T, I]
__device__ bf16 g_Xlo[(size_t)T_TOK * I_DIM];

// ---------------- helpers ----------------------------------------------------
__device__ __forceinline__ uint32_t smem_u32(const void* p) {
    return (uint32_t)__cvta_generic_to_shared(p);
}
__device__ __forceinline__ void cp16(uint32_t dst, const void* src) {
    asm volatile("cp.async.cg.shared.global [%0], [%1], 16;" :: "r"(dst), "l"(src));
}
__device__ __forceinline__ void cp_commit() {
    asm volatile("cp.async.commit_group;" ::: "memory");
}
template <int N>
__device__ __forceinline__ void cp_wait() {
    asm volatile("cp.async.wait_group %0;" :: "n"(N) : "memory");
}
__device__ __forceinline__ void ldsm_x4(uint32_t* r, uint32_t addr) {
    asm volatile("ldmatrix.sync.aligned.m8n8.x4.shared.b16 {%0,%1,%2,%3}, [%4];"
                 : "=r"(r[0]), "=r"(r[1]), "=r"(r[2]), "=r"(r[3]) : "r"(addr));
}
__device__ __forceinline__ void mma16816(float* d, const uint32_t* a,
                                         uint32_t b0, uint32_t b1) {
    asm volatile(
        "mma.sync.aligned.m16n8k16.row.col.f32.bf16.bf16.f32 "
        "{%0,%1,%2,%3}, {%4,%5,%6,%7}, {%8,%9}, {%0,%1,%2,%3};"
        : "+f"(d[0]), "+f"(d[1]), "+f"(d[2]), "+f"(d[3])
        : "r"(a[0]), "r"(a[1]), "r"(a[2]), "r"(a[3]), "r"(b0), "r"(b1));
}
__device__ __forceinline__ uint32_t pk2(bf16 a, bf16 b) {
    __nv_bfloat162 t; t.x = a; t.y = b;
    return *reinterpret_cast<uint32_t*>(&t);
}
__device__ __forceinline__ void split1(float a, bf16& h, bf16& l) {
    h = __float2bfloat16_rn(a);
    l = __float2bfloat16_rn(a - __bfloat162float(h));
}

// SMEM stage layout (pad rows to 80B to kill ldmatrix bank conflicts):
//   Ahi @0 (128x80=10240), Alo @10240, Bhi @20480 (128x80), Blo @30720
#define ROWB        80
#define STAGE_BYTES 40960
#define NSTAGE      4
#define SMEM_BYTES  (NSTAGE * STAGE_BYTES)

// ============================================================================
// GEMM1: hidden[T,H] x Wgu^T[2I,H] -> silu(gate)*up -> Xhi/Xlo [T,I]
// CTA: 128 tokens x 64 I-cols (gate + up). 8 warps (2 m x 4 n).
// ============================================================================
__device__ __forceinline__ void g1_load_stage(
    uint32_t SB, int k0, int bm, int nt,
    const bf16* __restrict__ Ahi, const bf16* __restrict__ Alo,
    const bf16* __restrict__ Wh,  const bf16* __restrict__ Wl, int tid)
{
#pragma unroll
    for (int c = tid; c < 512; c += 256) {            // A: 128 rows x 4 chunks
        int row = c >> 2, kc = c & 3;
        uint32_t d = SB + row * ROWB + kc * 16;
        size_t gof = (size_t)(bm + row) * H_DIM + k0 + kc * 8;
        cp16(d,         Ahi + gof);
        cp16(d + 10240, Alo + gof);
    }
#pragma unroll
    for (int c = tid; c < 512; c += 256) {            // B: 64 gate + 64 up rows
        int row = c >> 2, kc = c & 3;
        int gr = (row < 64) ? (nt * 64 + row) : (I_DIM + nt * 64 + row - 64);
        uint32_t d = SB + 20480 + row * ROWB + kc * 16;
        size_t gof = (size_t)gr * H_DIM + k0 + kc * 8;
        cp16(d,         Wh + gof);
        cp16(d + 10240, Wl + gof);
    }
}

__global__ __launch_bounds__(256, 1)
void gemm1_k(const bf16* __restrict__ Ahi, const bf16* __restrict__ Alo,
             const bf16* __restrict__ Wh,  const bf16* __restrict__ Wl,
             bf16* __restrict__ Xhi, bf16* __restrict__ Xlo)
{
    extern __shared__ char smem[];
    const uint32_t sb = smem_u32(smem);
    const int tid = threadIdx.x, wid = tid >> 5, lane = tid & 31;
    const int warp_m = wid & 1, warp_n = wid >> 1;
    const int nt = blockIdx.x;                  // 0..11 (64 I-cols each)
    const int bm = blockIdx.y * 128;
    const int NITER = H_DIM / 32;               // 64

    float accg[4][2][4], accu[4][2][4];
#pragma unroll
    for (int mi = 0; mi < 4; mi++)
#pragma unroll
        for (int ni = 0; ni < 2; ni++)
#pragma unroll
            for (int v = 0; v < 4; v++) { accg[mi][ni][v] = 0.f; accu[mi][ni][v] = 0.f; }

    g1_load_stage(sb, 0, bm, nt, Ahi, Alo, Wh, Wl, tid); cp_commit();
    g1_load_stage(sb + STAGE_BYTES, 32, bm, nt, Ahi, Alo, Wh, Wl, tid); cp_commit();
    g1_load_stage(sb + 2 * STAGE_BYTES, 64, bm, nt, Ahi, Alo, Wh, Wl, tid); cp_commit();

    const int arow = lane & 15;
    const int acol = (lane >> 4) * 16;
    const int brow = (lane & 7) + ((lane >> 4) << 3);
    const int bcol = ((lane >> 3) & 1) * 16;

    for (int it = 0; it < NITER; ++it) {
        cp_wait<2>();
        __syncthreads();
        if (it + 3 < NITER) {
            g1_load_stage(sb + ((it + 3) % NSTAGE) * STAGE_BYTES, (it + 3) * 32,
                          bm, nt, Ahi, Alo, Wh, Wl, tid);
        }
        cp_commit();   // keep group count in lockstep even when empty

        uint32_t SB = sb + (it % NSTAGE) * STAGE_BYTES;
#pragma unroll
        for (int ks = 0; ks < 2; ks++) {
            uint32_t ah[4][4], al[4][4];
#pragma unroll
            for (int mi = 0; mi < 4; mi++) {
                uint32_t ra = SB + (warp_m * 64 + mi * 16 + arow) * ROWB + ks * 32 + acol;
                ldsm_x4(ah[mi], ra);
                ldsm_x4(al[mi], ra + 10240);
            }
            uint32_t rb = SB + 20480 + (warp_n * 16 + brow) * ROWB + ks * 32 + bcol;
            uint32_t bgh[4], bgl[4], buh[4], bul[4];
            ldsm_x4(bgh, rb);
            ldsm_x4(bgl, rb + 10240);
            ldsm_x4(buh, rb + 64 * ROWB);
            ldsm_x4(bul, rb + 64 * ROWB + 10240);

            // term-outer ordering: 16 independent MMAs between accumulator reuse
#pragma unroll
            for (int mi = 0; mi < 4; mi++)
#pragma unroll
                for (int ni = 0; ni < 2; ni++) {
                    mma16816(accg[mi][ni], ah[mi], bgh[ni*2], bgh[ni*2+1]);
                    mma16816(accu[mi][ni], ah[mi], buh[ni*2], buh[ni*2+1]);
                }
#pragma unroll
            for (int mi = 0; mi < 4; mi++)
#pragma unroll
                for (int ni = 0; ni < 2; ni++) {
                    mma16816(accg[mi][ni], ah[mi], bgl[ni*2], bgl[ni*2+1]);
                    mma16816(accu[mi][ni], ah[mi], bul[ni*2], bul[ni*2+1]);
                }
#pragma unroll
            for (int mi = 0; mi < 4; mi++)
#pragma unroll
                for (int ni = 0; ni < 2; ni++) {
                    mma16816(accg[mi][ni], al[mi], bgh[ni*2], bgh[ni*2+1]);
                    mma16816(accu[mi][ni], al[mi], buh[ni*2], buh[ni*2+1]);
                }
        }
        __syncthreads();
    }

    // epilogue: silu(gate)*up, split, store packed pairs
    const int g = lane >> 2, t = lane & 3;
#pragma unroll
    for (int mi = 0; mi < 4; mi++)
#pragma unroll
        for (int ni = 0; ni < 2; ni++) {
            int col = nt * 64 + warp_n * 16 + ni * 8 + t * 2;
            int row0 = bm + warp_m * 64 + mi * 16 + g;
#pragma unroll
            for (int h = 0; h < 2; h++) {           // h=0: c0,c1 ; h=1: c2,c3
                int row = row0 + h * 8;
                float g0 = accg[mi][ni][h*2],   g1 = accg[mi][ni][h*2+1];
                float u0 = accu[mi][ni][h*2],   u1 = accu[mi][ni][h*2+1];
                float x0 = u0 * g0 / (1.0f + __expf(-g0));
                float x1 = u1 * g1 / (1.0f + __expf(-g1));
                bf16 h0, l0, h1, l1;
                split1(x0, h0, l0); split1(x1, h1, l1);
                size_t o = (size_t)row * I_DIM + col;
                *reinterpret_cast<uint32_t*>(Xhi + o) = pk2(h0, h1);
                *reinterpret_cast<uint32_t*>(Xlo + o) = pk2(l0, l1);
            }
        }
}

// ============================================================================
// GEMM2: X[T,I] x Wd^T[H,I] -> out[T,H] fp32
// CTA: 128 tokens x 128 H-cols. 8 warps (2 m x 4 n), warp 64x32.
// ============================================================================
__device__ __forceinline__ void g2_load_stage(
    uint32_t SB, int k0, int bm, int bn,
    const bf16* __restrict__ Xh, const bf16* __restrict__ Xl,
    const bf16* __restrict__ Dh, const bf16* __restrict__ Dl, int tid)
{
#pragma unroll
    for (int c = tid; c < 512; c += 256) {
        int row = c >> 2, kc = c & 3;
        uint32_t d = SB + row * ROWB + kc * 16;
        size_t gof = (size_t)(bm + row) * I_DIM + k0 + kc * 8;
        cp16(d,         Xh + gof);
        cp16(d + 10240, Xl + gof);
    }
#pragma unroll
    for (int c = tid; c < 512; c += 256) {
        int row = c >> 2, kc = c & 3;
        uint32_t d = SB + 20480 + row * ROWB + kc * 16;
        size_t gof = (size_t)(bn + row) * I_DIM + k0 + kc * 8;
        cp16(d,         Dh + gof);
        cp16(d + 10240, Dl + gof);
    }
}

__global__ __launch_bounds__(256, 1)
void gemm2_k(const bf16* __restrict__ Xh, const bf16* __restrict__ Xl,
             const bf16* __restrict__ Dh, const bf16* __restrict__ Dl,
             float* __restrict__ out)
{
    extern __shared__ char smem[];
    const uint32_t sb = smem_u32(smem);
    const int tid = threadIdx.x, wid = tid >> 5, lane = tid & 31;
    const int warp_m = wid & 1, warp_n = wid >> 1;
    const int bn = blockIdx.x * 128;
    const int bm = blockIdx.y * 128;
    const int NITER = I_DIM / 32;               // 24

    float acc[4][4][4];
#pragma unroll
    for (int mi = 0; mi < 4; mi++)
#pragma unroll
        for (int ni = 0; ni < 4; ni++)
#pragma unroll
            for (int v = 0; v < 4; v++) acc[mi][ni][v] = 0.f;

    g2_load_stage(sb, 0, bm, bn, Xh, Xl, Dh, Dl, tid); cp_commit();
    g2_load_stage(sb + STAGE_BYTES, 32, bm, bn, Xh, Xl, Dh, Dl, tid); cp_commit();
    g2_load_stage(sb + 2 * STAGE_BYTES, 64, bm, bn, Xh, Xl, Dh, Dl, tid); cp_commit();

    const int arow = lane & 15;
    const int acol = (lane >> 4) * 16;
    const int brow = (lane & 7) + ((lane >> 4) << 3);
    const int bcol = ((lane >> 3) & 1) * 16;

    for (int it = 0; it < NITER; ++it) {
        cp_wait<2>();
        __syncthreads();
        if (it + 3 < NITER) {
            g2_load_stage(sb + ((it + 3) % NSTAGE) * STAGE_BYTES, (it + 3) * 32,
                          bm, bn, Xh, Xl, Dh, Dl, tid);
        }
        cp_commit();

        uint32_t SB = sb + (it % NSTAGE) * STAGE_BYTES;
#pragma unroll
        for (int ks = 0; ks < 2; ks++) {
            uint32_t ah[4][4], al[4][4];
#pragma unroll
            for (int mi = 0; mi < 4; mi++) {
                uint32_t ra = SB + (warp_m * 64 + mi * 16 + arow) * ROWB + ks * 32 + acol;
                ldsm_x4(ah[mi], ra);
                ldsm_x4(al[mi], ra + 10240);
            }
            uint32_t bh[8], bl[8];
#pragma unroll
            for (int bq = 0; bq < 2; bq++) {
                uint32_t rb = SB + 20480 + (warp_n * 32 + bq * 16 + brow) * ROWB + ks * 32 + bcol;
                ldsm_x4(&bh[bq*4], rb);
                ldsm_x4(&bl[bq*4], rb + 10240);
            }

            // term-outer ordering: 16 independent MMAs between accumulator reuse
#pragma unroll
            for (int mi = 0; mi < 4; mi++)
#pragma unroll
                for (int ni = 0; ni < 4; ni++)
                    mma16816(acc[mi][ni], ah[mi], bh[ni*2], bh[ni*2+1]);
#pragma unroll
            for (int mi = 0; mi < 4; mi++)
#pragma unroll
                for (int ni = 0; ni < 4; ni++)
                    mma16816(acc[mi][ni], ah[mi], bl[ni*2], bl[ni*2+1]);
#pragma unroll
            for (int mi = 0; mi < 4; mi++)
#pragma unroll
                for (int ni = 0; ni < 4; ni++)
                    mma16816(acc[mi][ni], al[mi], bh[ni*2], bh[ni*2+1]);
        }
        __syncthreads();
    }

    const int g = lane >> 2, t = lane & 3;
#pragma unroll
    for (int mi = 0; mi < 4; mi++)
#pragma unroll
        for (int ni = 0; ni < 4; ni++) {
            int col = bn + warp_n * 32 + ni * 8 + t * 2;
            int row0 = bm + warp_m * 64 + mi * 16 + g;
            float2 v0 = make_float2(acc[mi][ni][0], acc[mi][ni][1]);
            float2 v1 = make_float2(acc[mi][ni][2], acc[mi][ni][3]);
            *reinterpret_cast<float2*>(out + (size_t)row0 * H_DIM + col) = v0;
            *reinterpret_cast<float2*>(out + (size_t)(row0 + 8) * H_DIM + col) = v1;
        }
}

// ---------------- prep kernels ----------------------------------------------
__global__ void split_hidden_k(const float* __restrict__ in,
                               bf16* __restrict__ hi, bf16* __restrict__ lo)
{
    size_t i = (size_t)blockIdx.x * blockDim.x + threadIdx.x;
    float4 v = reinterpret_cast<const float4*>(in)[i];
    bf16 h0, l0, h1, l1, h2, l2, h3, l3;
    split1(v.x, h0, l0); split1(v.y, h1, l1);
    split1(v.z, h2, l2); split1(v.w, h3, l3);
    uint2 ph; ph.x = pk2(h0, h1); ph.y = pk2(h2, h3);
    uint2 pl; pl.x = pk2(l0, l1); pl.y = pk2(l2, l3);
    reinterpret_cast<uint2*>(hi)[i] = ph;
    reinterpret_cast<uint2*>(lo)[i] = pl;
}

__global__ void transpose_split_k(const float* __restrict__ in,
                                  bf16* __restrict__ ohi, bf16* __restrict__ olo,
                                  int R, int C)
{
    __shared__ float t[32][33];
    int bx = blockIdx.x * 32, by = blockIdx.y * 32;
    int tx = threadIdx.x, ty = threadIdx.y;
#pragma unroll
    for (int j = 0; j < 32; j += 8)
        t[ty + j][tx] = in[(size_t)(by + ty + j) * C + bx + tx];
    __syncthreads();
#pragma unroll
    for (int j = 0; j < 32; j += 8) {
        float a = t[tx][ty + j];
        bf16 h, l; split1(a, h, l);
        size_t o = (size_t)(bx + ty + j) * R + by + tx;
        ohi[o] = h; olo[o] = l;
    }
}

// ---------------- host ------------------------------------------------------
extern "C" void kernel_launch(void* const* d_in, const int* in_sizes, int n_in,
                              void* d_out, int out_size)
{
    const float* hidden = (const float*)d_in[0];   // [T, H]
    const float* wgu    = (const float*)d_in[1];   // [H, 2I]
    const float* wd     = (const float*)d_in[2];   // [I, H]
    float* out = (float*)d_out;                    // [T, H]

    bf16 *Ahi, *Alo, *Wh, *Wl, *Dh, *Dl, *Xh, *Xl;
    cudaGetSymbolAddress((void**)&Ahi, g_Ahi);
    cudaGetSymbolAddress((void**)&Alo, g_Alo);
    cudaGetSymbolAddress((void**)&Wh,  g_Wgu_hi);
    cudaGetSymbolAddress((void**)&Wl,  g_Wgu_lo);
    cudaGetSymbolAddress((void**)&Dh,  g_Wd_hi);
    cudaGetSymbolAddress((void**)&Dl,  g_Wd_lo);
    cudaGetSymbolAddress((void**)&Xh,  g_Xhi);
    cudaGetSymbolAddress((void**)&Xl,  g_Xlo);

    cudaFuncSetAttribute(gemm1_k, cudaFuncAttributeMaxDynamicSharedMemorySize, SMEM_BYTES);
    cudaFuncSetAttribute(gemm2_k, cudaFuncAttributeMaxDynamicSharedMemorySize, SMEM_BYTES);

    split_hidden_k<<<(int)(((size_t)T_TOK * H_DIM / 4) / 256), 256>>>(hidden, Ahi, Alo);
    transpose_split_k<<<dim3(2 * I_DIM / 32, H_DIM / 32), dim3(32, 8)>>>(wgu, Wh, Wl, H_DIM, 2 * I_DIM);
    transpose_split_k<<<dim3(H_DIM / 32, I_DIM / 32), dim3(32, 8)>>>(wd, Dh, Dl, I_DIM, H_DIM);

    gemm1_k<<<dim3(I_DIM / 64, T_TOK / 128), 256, SMEM_BYTES>>>(Ahi, Alo, Wh, Wl, Xh, Xl);
    gemm2_k<<<dim3(H_DIM / 128, T_TOK / 128), 256, SMEM_BYTES>>>(Xh, Xl, Dh, Dl, out);
}

// round 6
// speedup vs baseline: 2.3913x; 1.1382x over previous
#include <cuda_runtime.h>
#include <cuda_bf16.h>
#include <cstdint>

#define T_TOK 32768
#define H_DIM 2048
#define I_DIM 768

using bf16 = __nv_bfloat16;

// ---------------- static device scratch ------------------------------------
__device__ bf16 g_Ahi[(size_t)T_TOK * H_DIM];
__device__ bf16 g_Alo[(size_t)T_TOK * H_DIM];
__device__ bf16 g_Wgu_hi[(size_t)2 * I_DIM * H_DIM];   // w_gate_up^T  [2I, H]
__device__ bf16 g_Wgu_lo[(size_t)2 * I_DIM * H_DIM];
__device__ bf16 g_Wd_hi[(size_t)H_DIM * I_DIM];        // w_down^T     [H, I]
__device__ bf16 g_Wd_lo[(size_t)H_DIM * I_DIM];
__device__ bf16 g_Xhi[(size_t)T_TOK * I_DIM];          // silu(g)*u    [T, I]
__device__ bf16 g_Xlo[(size_t)T_TOK * I_DIM];

// ---------------- helpers ----------------------------------------------------
__device__ __forceinline__ uint32_t smem_u32(const void* p) {
    return (uint32_t)__cvta_generic_to_shared(p);
}
__device__ __forceinline__ void cp16(uint32_t dst, const void* src) {
    asm volatile("cp.async.cg.shared.global [%0], [%1], 16;" :: "r"(dst), "l"(src));
}
__device__ __forceinline__ void cp_commit() {
    asm volatile("cp.async.commit_group;" ::: "memory");
}
template <int N>
__device__ __forceinline__ void cp_wait() {
    asm volatile("cp.async.wait_group %0;" :: "n"(N) : "memory");
}
__device__ __forceinline__ void ldsm_x4(uint32_t* r, uint32_t addr) {
    asm volatile("ldmatrix.sync.aligned.m8n8.x4.shared.b16 {%0,%1,%2,%3}, [%4];"
                 : "=r"(r[0]), "=r"(r[1]), "=r"(r[2]), "=r"(r[3]) : "r"(addr));
}
__device__ __forceinline__ void mma16816(float* d, const uint32_t* a,
                                         uint32_t b0, uint32_t b1) {
    asm volatile(
        "mma.sync.aligned.m16n8k16.row.col.f32.bf16.bf16.f32 "
        "{%0,%1,%2,%3}, {%4,%5,%6,%7}, {%8,%9}, {%0,%1,%2,%3};"
        : "+f"(d[0]), "+f"(d[1]), "+f"(d[2]), "+f"(d[3])
        : "r"(a[0]), "r"(a[1]), "r"(a[2]), "r"(a[3]), "r"(b0), "r"(b1));
}
__device__ __forceinline__ uint32_t pk2(bf16 a, bf16 b) {
    __nv_bfloat162 t; t.x = a; t.y = b;
    return *reinterpret_cast<uint32_t*>(&t);
}
__device__ __forceinline__ void split1(float a, bf16& h, bf16& l) {
    h = __float2bfloat16_rn(a);
    l = __float2bfloat16_rn(a - __bfloat162float(h));
}

// SMEM stage layout (pad rows to 80B to kill ldmatrix bank conflicts):
//   Ahi @0 (128x80=10240), Alo @10240, Bhi @20480 (128x80), Blo @30720
#define ROWB        80
#define STAGE_BYTES 40960
#define NSTAGE      2
#define SMEM_BYTES  (NSTAGE * STAGE_BYTES)

// ============================================================================
// GEMM1: hidden[T,H] x Wgu^T[2I,H] -> silu(gate)*up -> Xhi/Xlo [T,I]
// CTA: 128 tokens x 64 I-cols (gate + up). 8 warps (2 m x 4 n).
// ============================================================================
__device__ __forceinline__ void g1_load_stage(
    uint32_t SB, int k0, int bm, int nt,
    const bf16* __restrict__ Ahi, const bf16* __restrict__ Alo,
    const bf16* __restrict__ Wh,  const bf16* __restrict__ Wl, int tid)
{
#pragma unroll
    for (int c = tid; c < 512; c += 256) {            // A: 128 rows x 4 chunks
        int row = c >> 2, kc = c & 3;
        uint32_t d = SB + row * ROWB + kc * 16;
        size_t gof = (size_t)(bm + row) * H_DIM + k0 + kc * 8;
        cp16(d,         Ahi + gof);
        cp16(d + 10240, Alo + gof);
    }
#pragma unroll
    for (int c = tid; c < 512; c += 256) {            // B: 64 gate + 64 up rows
        int row = c >> 2, kc = c & 3;
        int gr = (row < 64) ? (nt * 64 + row) : (I_DIM + nt * 64 + row - 64);
        uint32_t d = SB + 20480 + row * ROWB + kc * 16;
        size_t gof = (size_t)gr * H_DIM + k0 + kc * 8;
        cp16(d,         Wh + gof);
        cp16(d + 10240, Wl + gof);
    }
}

__global__ __launch_bounds__(256, 2)
void gemm1_k(const bf16* __restrict__ Ahi, const bf16* __restrict__ Alo,
             const bf16* __restrict__ Wh,  const bf16* __restrict__ Wl,
             bf16* __restrict__ Xhi, bf16* __restrict__ Xlo)
{
    extern __shared__ char smem[];
    const uint32_t sb = smem_u32(smem);
    const int tid = threadIdx.x, wid = tid >> 5, lane = tid & 31;
    const int warp_m = wid & 1, warp_n = wid >> 1;
    const int nt = blockIdx.x;                  // 0..11 (64 I-cols each)
    const int bm = blockIdx.y * 128;
    const int NITER = H_DIM / 32;               // 64

    float accg[4][2][4], accu[4][2][4];
#pragma unroll
    for (int mi = 0; mi < 4; mi++)
#pragma unroll
        for (int ni = 0; ni < 2; ni++)
#pragma unroll
            for (int v = 0; v < 4; v++) { accg[mi][ni][v] = 0.f; accu[mi][ni][v] = 0.f; }

    g1_load_stage(sb, 0, bm, nt, Ahi, Alo, Wh, Wl, tid); cp_commit();
    g1_load_stage(sb + STAGE_BYTES, 32, bm, nt, Ahi, Alo, Wh, Wl, tid); cp_commit();

    const int arow = lane & 15;
    const int acol = (lane >> 4) * 16;
    const int brow = (lane & 7) + ((lane >> 4) << 3);
    const int bcol = ((lane >> 3) & 1) * 16;

    for (int it = 0; it < NITER; ++it) {
        cp_wait<1>();
        __syncthreads();

        uint32_t SB = sb + (it & 1) * STAGE_BYTES;
#pragma unroll
        for (int ks = 0; ks < 2; ks++) {
            // B fragments (gate hi/lo, up hi/lo): 16 regs, live across passes
            uint32_t rb = SB + 20480 + (warp_n * 16 + brow) * ROWB + ks * 32 + bcol;
            uint32_t bgh[4], bgl[4], buh[4], bul[4];
            ldsm_x4(bgh, rb);
            ldsm_x4(bgl, rb + 10240);
            ldsm_x4(buh, rb + 64 * ROWB);
            ldsm_x4(bul, rb + 64 * ROWB + 10240);

            // A hi fragments: 16 regs (reused below for lo)
            uint32_t af[4][4];
#pragma unroll
            for (int mi = 0; mi < 4; mi++) {
                uint32_t ra = SB + (warp_m * 64 + mi * 16 + arow) * ROWB + ks * 32 + acol;
                ldsm_x4(af[mi], ra);
            }
            // pass 1: hi * B_hi
#pragma unroll
            for (int mi = 0; mi < 4; mi++)
#pragma unroll
                for (int ni = 0; ni < 2; ni++) {
                    mma16816(accg[mi][ni], af[mi], bgh[ni*2], bgh[ni*2+1]);
                    mma16816(accu[mi][ni], af[mi], buh[ni*2], buh[ni*2+1]);
                }
            // pass 2: hi * B_lo
#pragma unroll
            for (int mi = 0; mi < 4; mi++)
#pragma unroll
                for (int ni = 0; ni < 2; ni++) {
                    mma16816(accg[mi][ni], af[mi], bgl[ni*2], bgl[ni*2+1]);
                    mma16816(accu[mi][ni], af[mi], bul[ni*2], bul[ni*2+1]);
                }
            // reload A lo into same regs
#pragma unroll
            for (int mi = 0; mi < 4; mi++) {
                uint32_t ra = SB + (warp_m * 64 + mi * 16 + arow) * ROWB + ks * 32 + acol;
                ldsm_x4(af[mi], ra + 10240);
            }
            // pass 3: lo * B_hi
#pragma unroll
            for (int mi = 0; mi < 4; mi++)
#pragma unroll
                for (int ni = 0; ni < 2; ni++) {
                    mma16816(accg[mi][ni], af[mi], bgh[ni*2], bgh[ni*2+1]);
                    mma16816(accu[mi][ni], af[mi], buh[ni*2], buh[ni*2+1]);
                }
        }
        __syncthreads();
        if (it + 2 < NITER) {
            g1_load_stage(sb + (it & 1) * STAGE_BYTES, (it + 2) * 32,
                          bm, nt, Ahi, Alo, Wh, Wl, tid);
        }
        cp_commit();   // keep group count in lockstep even when empty
    }

    // epilogue: silu(gate)*up, split, store packed pairs
    const int g = lane >> 2, t = lane & 3;
#pragma unroll
    for (int mi = 0; mi < 4; mi++)
#pragma unroll
        for (int ni = 0; ni < 2; ni++) {
            int col = nt * 64 + warp_n * 16 + ni * 8 + t * 2;
            int row0 = bm + warp_m * 64 + mi * 16 + g;
#pragma unroll
            for (int h = 0; h < 2; h++) {           // h=0: c0,c1 ; h=1: c2,c3
                int row = row0 + h * 8;
                float g0 = accg[mi][ni][h*2],   g1 = accg[mi][ni][h*2+1];
                float u0 = accu[mi][ni][h*2],   u1 = accu[mi][ni][h*2+1];
                float x0 = u0 * g0 / (1.0f + __expf(-g0));
                float x1 = u1 * g1 / (1.0f + __expf(-g1));
                bf16 h0, l0, h1, l1;
                split1(x0, h0, l0); split1(x1, h1, l1);
                size_t o = (size_t)row * I_DIM + col;
                *reinterpret_cast<uint32_t*>(Xhi + o) = pk2(h0, h1);
                *reinterpret_cast<uint32_t*>(Xlo + o) = pk2(l0, l1);
            }
        }
}

// ============================================================================
// GEMM2: X[T,I] x Wd^T[H,I] -> out[T,H] fp32
// CTA: 128 tokens x 128 H-cols. 8 warps (2 m x 4 n), warp 64x32.
// ============================================================================
__device__ __forceinline__ void g2_load_stage(
    uint32_t SB, int k0, int bm, int bn,
    const bf16* __restrict__ Xh, const bf16* __restrict__ Xl,
    const bf16* __restrict__ Dh, const bf16* __restrict__ Dl, int tid)
{
#pragma unroll
    for (int c = tid; c < 512; c += 256) {
        int row = c >> 2, kc = c & 3;
        uint32_t d = SB + row * ROWB + kc * 16;
        size_t gof = (size_t)(bm + row) * I_DIM + k0 + kc * 8;
        cp16(d,         Xh + gof);
        cp16(d + 10240, Xl + gof);
    }
#pragma unroll
    for (int c = tid; c < 512; c += 256) {
        int row = c >> 2, kc = c & 3;
        uint32_t d = SB + 20480 + row * ROWB + kc * 16;
        size_t gof = (size_t)(bn + row) * I_DIM + k0 + kc * 8;
        cp16(d,         Dh + gof);
        cp16(d + 10240, Dl + gof);
    }
}

__global__ __launch_bounds__(256, 2)
void gemm2_k(const bf16* __restrict__ Xh, const bf16* __restrict__ Xl,
             const bf16* __restrict__ Dh, const bf16* __restrict__ Dl,
             float* __restrict__ out)
{
    extern __shared__ char smem[];
    const uint32_t sb = smem_u32(smem);
    const int tid = threadIdx.x, wid = tid >> 5, lane = tid & 31;
    const int warp_m = wid & 1, warp_n = wid >> 1;
    const int bn = blockIdx.x * 128;
    const int bm = blockIdx.y * 128;
    const int NITER = I_DIM / 32;               // 24

    float acc[4][4][4];
#pragma unroll
    for (int mi = 0; mi < 4; mi++)
#pragma unroll
        for (int ni = 0; ni < 4; ni++)
#pragma unroll
            for (int v = 0; v < 4; v++) acc[mi][ni][v] = 0.f;

    g2_load_stage(sb, 0, bm, bn, Xh, Xl, Dh, Dl, tid); cp_commit();
    g2_load_stage(sb + STAGE_BYTES, 32, bm, bn, Xh, Xl, Dh, Dl, tid); cp_commit();

    const int arow = lane & 15;
    const int acol = (lane >> 4) * 16;
    const int brow = (lane & 7) + ((lane >> 4) << 3);
    const int bcol = ((lane >> 3) & 1) * 16;

    for (int it = 0; it < NITER; ++it) {
        cp_wait<1>();
        __syncthreads();

        uint32_t SB = sb + (it & 1) * STAGE_BYTES;
#pragma unroll
        for (int ks = 0; ks < 2; ks++) {
            uint32_t bh[8], bl[8];
#pragma unroll
            for (int bq = 0; bq < 2; bq++) {
                uint32_t rb = SB + 20480 + (warp_n * 32 + bq * 16 + brow) * ROWB + ks * 32 + bcol;
                ldsm_x4(&bh[bq*4], rb);
                ldsm_x4(&bl[bq*4], rb + 10240);
            }
            uint32_t af[4][4];
#pragma unroll
            for (int mi = 0; mi < 4; mi++) {
                uint32_t ra = SB + (warp_m * 64 + mi * 16 + arow) * ROWB + ks * 32 + acol;
                ldsm_x4(af[mi], ra);
            }
            // pass 1: hi * B_hi
#pragma unroll
            for (int mi = 0; mi < 4; mi++)
#pragma unroll
                for (int ni = 0; ni < 4; ni++)
                    mma16816(acc[mi][ni], af[mi], bh[ni*2], bh[ni*2+1]);
            // pass 2: hi * B_lo
#pragma unroll
            for (int mi = 0; mi < 4; mi++)
#pragma unroll
                for (int ni = 0; ni < 4; ni++)
                    mma16816(acc[mi][ni], af[mi], bl[ni*2], bl[ni*2+1]);
            // reload A lo
#pragma unroll
            for (int mi = 0; mi < 4; mi++) {
                uint32_t ra = SB + (warp_m * 64 + mi * 16 + arow) * ROWB + ks * 32 + acol;
                ldsm_x4(af[mi], ra + 10240);
            }
            // pass 3: lo * B_hi
#pragma unroll
            for (int mi = 0; mi < 4; mi++)
#pragma unroll
                for (int ni = 0; ni < 4; ni++)
                    mma16816(acc[mi][ni], af[mi], bh[ni*2], bh[ni*2+1]);
        }
        __syncthreads();
        if (it + 2 < NITER) {
            g2_load_stage(sb + (it & 1) * STAGE_BYTES, (it + 2) * 32,
                          bm, bn, Xh, Xl, Dh, Dl, tid);
        }
        cp_commit();
    }

    const int g = lane >> 2, t = lane & 3;
#pragma unroll
    for (int mi = 0; mi < 4; mi++)
#pragma unroll
        for (int ni = 0; ni < 4; ni++) {
            int col = bn + warp_n * 32 + ni * 8 + t * 2;
            int row0 = bm + warp_m * 64 + mi * 16 + g;
            float2 v0 = make_float2(acc[mi][ni][0], acc[mi][ni][1]);
            float2 v1 = make_float2(acc[mi][ni][2], acc[mi][ni][3]);
            *reinterpret_cast<float2*>(out + (size_t)row0 * H_DIM + col) = v0;
            *reinterpret_cast<float2*>(out + (size_t)(row0 + 8) * H_DIM + col) = v1;
        }
}

// ---------------- prep kernels ----------------------------------------------
__global__ void split_hidden_k(const float* __restrict__ in,
                               bf16* __restrict__ hi, bf16* __restrict__ lo)
{
    size_t i = (size_t)blockIdx.x * blockDim.x + threadIdx.x;
    float4 v = reinterpret_cast<const float4*>(in)[i];
    bf16 h0, l0, h1, l1, h2, l2, h3, l3;
    split1(v.x, h0, l0); split1(v.y, h1, l1);
    split1(v.z, h2, l2); split1(v.w, h3, l3);
    uint2 ph; ph.x = pk2(h0, h1); ph.y = pk2(h2, h3);
    uint2 pl; pl.x = pk2(l0, l1); pl.y = pk2(l2, l3);
    reinterpret_cast<uint2*>(hi)[i] = ph;
    reinterpret_cast<uint2*>(lo)[i] = pl;
}

__global__ void transpose_split_k(const float* __restrict__ in,
                                  bf16* __restrict__ ohi, bf16* __restrict__ olo,
                                  int R, int C)
{
    __shared__ float t[32][33];
    int bx = blockIdx.x * 32, by = blockIdx.y * 32;
    int tx = threadIdx.x, ty = threadIdx.y;
#pragma unroll
    for (int j = 0; j < 32; j += 8)
        t[ty + j][tx] = in[(size_t)(by + ty + j) * C + bx + tx];
    __syncthreads();
#pragma unroll
    for (int j = 0; j < 32; j += 8) {
        float a = t[tx][ty + j];
        bf16 h, l; split1(a, h, l);
        size_t o = (size_t)(bx + ty + j) * R + by + tx;
        ohi[o] = h; olo[o] = l;
    }
}

// ---------------- host ------------------------------------------------------
extern "C" void kernel_launch(void* const* d_in, const int* in_sizes, int n_in,
                              void* d_out, int out_size)
{
    const float* hidden = (const float*)d_in[0];   // [T, H]
    const float* wgu    = (const float*)d_in[1];   // [H, 2I]
    const float* wd     = (const float*)d_in[2];   // [I, H]
    float* out = (float*)d_out;                    // [T, H]

    bf16 *Ahi, *Alo, *Wh, *Wl, *Dh, *Dl, *Xh, *Xl;
    cudaGetSymbolAddress((void**)&Ahi, g_Ahi);
    cudaGetSymbolAddress((void**)&Alo, g_Alo);
    cudaGetSymbolAddress((void**)&Wh,  g_Wgu_hi);
    cudaGetSymbolAddress((void**)&Wl,  g_Wgu_lo);
    cudaGetSymbolAddress((void**)&Dh,  g_Wd_hi);
    cudaGetSymbolAddress((void**)&Dl,  g_Wd_lo);
    cudaGetSymbolAddress((void**)&Xh,  g_Xhi);
    cudaGetSymbolAddress((void**)&Xl,  g_Xlo);

    cudaFuncSetAttribute(gemm1_k, cudaFuncAttributeMaxDynamicSharedMemorySize, SMEM_BYTES);
    cudaFuncSetAttribute(gemm2_k, cudaFuncAttributeMaxDynamicSharedMemorySize, SMEM_BYTES);

    split_hidden_k<<<(int)(((size_t)T_TOK * H_DIM / 4) / 256), 256>>>(hidden, Ahi, Alo);
    transpose_split_k<<<dim3(2 * I_DIM / 32, H_DIM / 32), dim3(32, 8)>>>(wgu, Wh, Wl, H_DIM, 2 * I_DIM);
    transpose_split_k<<<dim3(H_DIM / 32, I_DIM / 32), dim3(32, 8)>>>(wd, Dh, Dl, I_DIM, H_DIM);

    gemm1_k<<<dim3(I_DIM / 64, T_TOK / 128), 256, SMEM_BYTES>>>(Ahi, Alo, Wh, Wl, Xh, Xl);
    gemm2_k<<<dim3(H_DIM / 128, T_TOK / 128), 256, SMEM_BYTES>>>(Xh, Xl, Dh, Dl, out);
}